// round 14
// baseline (speedup 1.0000x reference)
#include <cuda_runtime.h>
#include <cuda_fp16.h>
#include <math.h>

#define BB 2
#define TT 2048
#define DD 1024
#define NH 16
#define DH 64
#define BT (BB*TT)

// fp16 scratch (allocation-free rule: __device__ globals)
__device__ __align__(16) __half g_h16[BT*DD];
__device__ __align__(16) __half g_w16[4][DD*DD];
__device__ __align__(16) __half g_Qh[BB*NH*TT*DH];
__device__ __align__(16) __half g_Kh[BB*NH*TT*DH];
__device__ __align__(16) __half g_Vh[BB*NH*TT*DH];
__device__ __align__(16) __half g_A16[BT*DD];
__device__ __align__(16) float2 g_rope[TT*32];     // (cos,sin) per (t,pair)

__device__ __forceinline__ unsigned pack_h2(float x, float y) {
    unsigned r;
    asm("cvt.rn.f16x2.f32 %0, %1, %2;" : "=r"(r) : "f"(y), "f"(x));
    return r;
}
__device__ __forceinline__ unsigned smem_u32(const void* p) {
    return (unsigned)__cvta_generic_to_shared(p);
}
__device__ __forceinline__ float fex2(float x) {
    float r;
    asm("ex2.approx.f32 %0, %1;" : "=f"(r) : "f"(x));
    return r;
}
#define H2EX2(d, s) asm("ex2.approx.f16x2 %0, %1;" : "=r"(d) : "r"(s))

#define MMA_F16(d0,d1,d2,d3,a0,a1,a2,a3,b0,b1)                                    \
    asm volatile("mma.sync.aligned.m16n8k16.row.col.f32.f16.f16.f32 "             \
                 "{%0,%1,%2,%3},{%4,%5,%6,%7},{%8,%9},{%0,%1,%2,%3};"             \
                 : "+f"(d0), "+f"(d1), "+f"(d2), "+f"(d3)                         \
                 : "r"(a0), "r"(a1), "r"(a2), "r"(a3), "r"(b0), "r"(b1))

#define LDSM_X4(r0,r1,r2,r3,addr)                                                 \
    asm volatile("ldmatrix.sync.aligned.m8n8.x4.shared.b16 "                      \
                 "{%0,%1,%2,%3}, [%4];"                                           \
                 : "=r"(r0), "=r"(r1), "=r"(r2), "=r"(r3) : "r"(addr))

#define LDSM_X4_TRANS(r0,r1,r2,r3,addr)                                           \
    asm volatile("ldmatrix.sync.aligned.m8n8.x4.trans.shared.b16 "                \
                 "{%0,%1,%2,%3}, [%4];"                                           \
                 : "=r"(r0), "=r"(r1), "=r"(r2), "=r"(r3) : "r"(addr))

#define LDSM_X2_TRANS(r0,r1,addr)                                                 \
    asm volatile("ldmatrix.sync.aligned.m8n8.x2.trans.shared.b16 "                \
                 "{%0,%1}, [%2];"                                                 \
                 : "=r"(r0), "=r"(r1) : "r"(addr))

#define CP_ASYNC16(dst, src)                                                      \
    asm volatile("cp.async.cg.shared.global [%0], [%1], 16;" :: "r"(dst), "l"(src))
#define CP_COMMIT() asm volatile("cp.async.commit_group;")
#define CP_WAIT0()  asm volatile("cp.async.wait_group 0;")
#define CP_WAIT1()  asm volatile("cp.async.wait_group 1;")

// ---------------------------------------------------------------------------
// fp32 -> fp16 conversion: segment 0 = h (4M), 1-4 = weights (1M each)
// ---------------------------------------------------------------------------
__global__ void cvt5(const float* __restrict__ h,  const float* __restrict__ wq,
                     const float* __restrict__ wk, const float* __restrict__ wv,
                     const float* __restrict__ wo)
{
    const float* src; __half* dst; int n;
    switch (blockIdx.y) {
        case 0: src = h;  dst = g_h16;     n = BT*DD; break;
        case 1: src = wq; dst = g_w16[0];  n = DD*DD; break;
        case 2: src = wk; dst = g_w16[1];  n = DD*DD; break;
        case 3: src = wv; dst = g_w16[2];  n = DD*DD; break;
        default:src = wo; dst = g_w16[3];  n = DD*DD; break;
    }
    const int idx = (blockIdx.x * blockDim.x + threadIdx.x) * 8;
    if (idx >= n) return;
    float4 v0 = *(const float4*)(src + idx);
    float4 v1 = *(const float4*)(src + idx + 4);
    uint4 u = make_uint4(pack_h2(v0.x, v0.y), pack_h2(v0.z, v0.w),
                         pack_h2(v1.x, v1.y), pack_h2(v1.z, v1.w));
    *(uint4*)&dst[idx] = u;
}

// RoPE (cos,sin) table: identical fp32 sincosf values the epilogue used inline.
__global__ void rope_fill()
{
    const int id = blockIdx.x * blockDim.x + threadIdx.x;   // [0, TT*32)
    const int pair = id & 31;
    const int t = id >> 5;
    const float freq = powf(10000.0f, -(float)pair * (1.0f/32.0f));
    float s, c;
    sincosf((float)t * freq, &s, &c);
    g_rope[id] = make_float2(c, s);
}

// ---------------------------------------------------------------------------
// fp16 cp.async GEMM NT (R9 winner config): C = A[M,K] * W[N,K]^T, fp32 accum.
// 128x128 tile, BK=64 (full SW128 rows), 3-stage cp.async pipeline,
// 256 thr = 8 warps (2x4), warp tile 64x32, m16n8k16 + ldmatrix.x4.
// MODE 0: fp32 C row-major.  MODE 1: fp16 C head layout + table-based RoPE.
// ---------------------------------------------------------------------------
#define BK64   64
#define NKT64  (DD/BK64)      // 16
#define OPB    16384          // bytes per operand tile (128 rows x 128B)
#define STG64  (2*OPB)        // 32768 bytes per stage (A+B)
#define GSMEM  (3*STG64)      // 98304

__device__ __forceinline__ unsigned swz128(int row, int chunk) {
    return (unsigned)(row << 7) + (unsigned)(((chunk ^ (row & 7)) & 7) << 4);
}

template<int MODE>
__device__ __forceinline__
void hgemm16_body(const __half* __restrict__ A, const __half* __restrict__ W,
                  float* __restrict__ Cf, __half* __restrict__ Ch,
                  int rowBase, int colBase, int doRope)
{
    extern __shared__ __half dsm[];
    const unsigned aSm = smem_u32(dsm);

    const int tid  = threadIdx.x;
    const int lane = tid & 31;
    const int warp = tid >> 5;
    const int grp  = lane >> 2;
    const int qk   = lane & 3;
    const int warpM = (warp & 1) * 64;
    const int warpN = (warp >> 1) * 32;
    const int lmRow = lane & 15;
    const int lmSel = lane >> 4;

    float acc[4][4][4];
#pragma unroll
    for (int mt = 0; mt < 4; ++mt)
#pragma unroll
        for (int nt = 0; nt < 4; ++nt)
#pragma unroll
            for (int r = 0; r < 4; ++r) acc[mt][nt][r] = 0.f;

    const __half* Ab = A + (size_t)rowBase * DD;
    const __half* Wb = W + (size_t)colBase * DD;

#define G_ISSUE(t, s)                                                         \
    do {                                                                      \
        const unsigned sb = aSm + (s) * STG64;                                \
        _Pragma("unroll")                                                     \
        for (int i = 0; i < 4; ++i) {                                         \
            const int id = tid + 256*i;                                       \
            const int r = id >> 3, c = id & 7;                                \
            const unsigned off = swz128(r, c);                                \
            const size_t g = (size_t)r * DD + (t)*BK64 + c*8;                 \
            CP_ASYNC16(sb + off,       Ab + g);                               \
            CP_ASYNC16(sb + OPB + off, Wb + g);                               \
        }                                                                     \
        CP_COMMIT();                                                          \
    } while (0)

    G_ISSUE(0, 0);
    G_ISSUE(1, 1);

    int buf = 0;
    for (int t = 0; t < NKT64; ++t) {
        if (t + 1 < NKT64) { CP_WAIT1(); } else { CP_WAIT0(); }
        __syncthreads();
        if (t + 2 < NKT64) G_ISSUE(t + 2, (t + 2) % 3);

        const unsigned ab = aSm + buf * STG64;
        const unsigned bb = ab + OPB;
#pragma unroll
        for (int kc = 0; kc < 4; ++kc) {
            const int ch = kc * 2 + lmSel;
            unsigned a[4][4];
#pragma unroll
            for (int mt = 0; mt < 4; ++mt)
                LDSM_X4(a[mt][0], a[mt][1], a[mt][2], a[mt][3],
                        ab + swz128(warpM + mt*16 + lmRow, ch));
            unsigned bl[4], bh[4];
#pragma unroll
            for (int nc = 0; nc < 2; ++nc) {
                unsigned x0, x1, x2, x3;
                LDSM_X4(x0, x1, x2, x3, bb + swz128(warpN + nc*16 + lmRow, ch));
                bl[2*nc] = x0; bl[2*nc+1] = x1;
                bh[2*nc] = x2; bh[2*nc+1] = x3;
            }
#pragma unroll
            for (int mt = 0; mt < 4; ++mt)
#pragma unroll
                for (int nt = 0; nt < 4; ++nt)
                    MMA_F16(acc[mt][nt][0], acc[mt][nt][1],
                            acc[mt][nt][2], acc[mt][nt][3],
                            a[mt][0], a[mt][1], a[mt][2], a[mt][3],
                            bl[nt], bh[nt]);
        }
        buf = (buf + 1) % 3;
    }
#undef G_ISSUE

#pragma unroll
    for (int mt = 0; mt < 4; ++mt) {
#pragma unroll
        for (int nt = 0; nt < 4; ++nt) {
            const int rr = rowBase + warpM + mt*16 + grp;
            const int c  = colBase + warpN + nt*8 + 2*qk;
            float2 v0 = make_float2(acc[mt][nt][0], acc[mt][nt][1]);
            float2 v1 = make_float2(acc[mt][nt][2], acc[mt][nt][3]);
            if (MODE == 0) {
                *(float2*)&Cf[(size_t)rr * DD + c]       = v0;
                *(float2*)&Cf[(size_t)(rr+8) * DD + c]   = v1;
            } else {
                const int hh = c / DH, d = c % DH;
                const int b0 = rr / TT, t0 = rr % TT;
                const int b1 = (rr+8) / TT, t1 = (rr+8) % TT;
                if (doRope) {
                    const int pair = d >> 1;
                    const float2 cs0 = g_rope[t0*32 + pair];
                    const float2 cs1 = g_rope[t1*32 + pair];
                    v0 = make_float2(cs0.x*v0.x - cs0.y*v0.y,
                                     cs0.y*v0.x + cs0.x*v0.y);
                    v1 = make_float2(cs1.x*v1.x - cs1.y*v1.y,
                                     cs1.y*v1.x + cs1.x*v1.y);
                }
                *(unsigned*)&Ch[(((size_t)(b0*NH + hh))*TT + t0)*DH + d] =
                    pack_h2(v0.x, v0.y);
                *(unsigned*)&Ch[(((size_t)(b1*NH + hh))*TT + t1)*DH + d] =
                    pack_h2(v1.x, v1.y);
            }
        }
    }
}

__global__ __launch_bounds__(256, 2)
void hgemm16_qkv()
{
    const int z = blockIdx.z;
    __half* C = (z == 0) ? g_Qh : (z == 1) ? g_Kh : g_Vh;
    hgemm16_body<1>(g_h16, g_w16[z], nullptr, C,
                    blockIdx.y * 128, blockIdx.x * 128, z < 2);
}

__global__ __launch_bounds__(256, 2)
void hgemm16_out(float* __restrict__ out)
{
    hgemm16_body<0>(g_A16, g_w16[3], out, nullptr,
                    blockIdx.y * 128, blockIdx.x * 128, 0);
}

// ---------------------------------------------------------------------------
// fp16 flash attention (R10/R11 winner, unchanged): log2-domain ex2 softmax,
// ones-column row-sum MMA, cp.async double-buffered K/V.
// ---------------------------------------------------------------------------
#define FKST  72
#define FTILE (64*FKST*2)

__global__ __launch_bounds__(256, 2)
void flash16()
{
    __shared__ __half sK[2*64*FKST];
    __shared__ __half sV[2*64*FKST];
    const unsigned kSm = smem_u32(sK);
    const unsigned vSm = smem_u32(sV);

    const int tid  = threadIdx.x;
    const int lane = tid & 31;
    const int warp = tid >> 5;
    const int grp  = lane >> 2;
    const int qk   = lane & 3;
    const int qtile = gridDim.x - 1 - blockIdx.x;
    const int bh    = blockIdx.y;
    const int qbase = qtile * 128;

    const __half* Qp = g_Qh + (size_t)bh * TT * DH;
    const __half* Kp = g_Kh + (size_t)bh * TT * DH;
    const __half* Vp = g_Vh + (size_t)bh * TT * DH;

    const int lmRow = lane & 15;
    const int lmSel = lane >> 4;

    const int qi0 = qbase + warp*16 + grp;
    const int qi1 = qi0 + 8;
    unsigned qa[4][4];
    {
        const __half* q0 = Qp + (size_t)qi0 * DH;
        const __half* q1 = Qp + (size_t)qi1 * DH;
#pragma unroll
        for (int kc = 0; kc < 4; ++kc) {
            qa[kc][0] = *(const unsigned*)(q0 + kc*16 + 2*qk);
            qa[kc][1] = *(const unsigned*)(q1 + kc*16 + 2*qk);
            qa[kc][2] = *(const unsigned*)(q0 + kc*16 + 8 + 2*qk);
            qa[kc][3] = *(const unsigned*)(q1 + kc*16 + 8 + 2*qk);
        }
    }

    float m0 = -1e30f, m1 = -1e30f;
    float oa[8][4];
    float oaS[4] = {0.f, 0.f, 0.f, 0.f};
#pragma unroll
    for (int nt = 0; nt < 8; ++nt)
#pragma unroll
        for (int r = 0; r < 4; ++r) oa[nt][r] = 0.f;

    if (tid < 128) {
        const int rr = tid & 63, ss = tid >> 6;
        *(uint4*)&sV[ss*64*FKST + rr*FKST + 64] = make_uint4(0x00003C00u, 0u, 0u, 0u);
    }

    const int fr = tid >> 3;
    const int fc = tid & 7;
    const unsigned dk0 = (fr*FKST + fc*8) * 2;
    const unsigned dk1 = ((fr+32)*FKST + fc*8) * 2;

#define F_ISSUE(kt, s)                                                        \
    do {                                                                      \
        const __half* ks_ = Kp + (size_t)((kt)*64 + fr) * DH + fc*8;          \
        const __half* vs_ = Vp + (size_t)((kt)*64 + fr) * DH + fc*8;          \
        CP_ASYNC16(kSm + (s)*FTILE + dk0, ks_);                               \
        CP_ASYNC16(kSm + (s)*FTILE + dk1, ks_ + (size_t)32*DH);               \
        CP_ASYNC16(vSm + (s)*FTILE + dk0, vs_);                               \
        CP_ASYNC16(vSm + (s)*FTILE + dk1, vs_ + (size_t)32*DH);               \
        CP_COMMIT();                                                          \
    } while (0)

    F_ISSUE(0, 0);

    const int lastKt = 2*qtile + 1;
    for (int kt = 0; kt <= lastKt; ++kt) {
        const int kbase = kt * 64;
        const int s = kt & 1;
        CP_WAIT0();
        __syncthreads();
        if (kt < lastKt) F_ISSUE(kt + 1, (kt + 1) & 1);

        float sa[8][4];
#pragma unroll
        for (int nt = 0; nt < 8; ++nt)
#pragma unroll
            for (int r = 0; r < 4; ++r) sa[nt][r] = 0.f;

#pragma unroll
        for (int kc = 0; kc < 4; ++kc) {
#pragma unroll
            for (int nc = 0; nc < 4; ++nc) {
                unsigned x0, x1, x2, x3;
                const unsigned addr = kSm + s*FTILE +
                    ((nc*16 + lmRow)*FKST + (kc*2 + lmSel)*8) * 2;
                LDSM_X4(x0, x1, x2, x3, addr);
                MMA_F16(sa[2*nc  ][0], sa[2*nc  ][1], sa[2*nc  ][2], sa[2*nc  ][3],
                        qa[kc][0], qa[kc][1], qa[kc][2], qa[kc][3], x0, x2);
                MMA_F16(sa[2*nc+1][0], sa[2*nc+1][1], sa[2*nc+1][2], sa[2*nc+1][3],
                        qa[kc][0], qa[kc][1], qa[kc][2], qa[kc][3], x1, x3);
            }
        }

        const float sc2 = 0.125f * 1.44269504f;
        if (kbase + 63 > qbase) {
#pragma unroll
            for (int nt = 0; nt < 8; ++nt) {
                const int c0 = kbase + nt*8 + 2*qk;
                const int c1 = c0 + 1;
                sa[nt][0] = (c0 <= qi0) ? sa[nt][0]*sc2 : -1e30f;
                sa[nt][1] = (c1 <= qi0) ? sa[nt][1]*sc2 : -1e30f;
                sa[nt][2] = (c0 <= qi1) ? sa[nt][2]*sc2 : -1e30f;
                sa[nt][3] = (c1 <= qi1) ? sa[nt][3]*sc2 : -1e30f;
            }
        } else {
#pragma unroll
            for (int nt = 0; nt < 8; ++nt)
#pragma unroll
                for (int r = 0; r < 4; ++r) sa[nt][r] *= sc2;
        }

        float mx0 = sa[0][0], mx1 = sa[0][2];
#pragma unroll
        for (int nt = 0; nt < 8; ++nt) {
            mx0 = fmaxf(mx0, fmaxf(sa[nt][0], sa[nt][1]));
            mx1 = fmaxf(mx1, fmaxf(sa[nt][2], sa[nt][3]));
        }
        mx0 = fmaxf(mx0, __shfl_xor_sync(0xffffffffu, mx0, 1));
        mx0 = fmaxf(mx0, __shfl_xor_sync(0xffffffffu, mx0, 2));
        mx1 = fmaxf(mx1, __shfl_xor_sync(0xffffffffu, mx1, 1));
        mx1 = fmaxf(mx1, __shfl_xor_sync(0xffffffffu, mx1, 2));

        const float nm0 = fmaxf(m0, mx0);
        const float nm1 = fmaxf(m1, mx1);
        const float al0 = fex2(m0 - nm0);
        const float al1 = fex2(m1 - nm1);
        m0 = nm0; m1 = nm1;

#pragma unroll
        for (int nt = 0; nt < 8; ++nt) {
            oa[nt][0] *= al0; oa[nt][1] *= al0;
            oa[nt][2] *= al1; oa[nt][3] *= al1;
        }
        oaS[0] *= al0; oaS[1] *= al0;
        oaS[2] *= al1; oaS[3] *= al1;

#pragma unroll
        for (int kc = 0; kc < 4; ++kc) {
            unsigned a0 = pack_h2(sa[2*kc  ][0] - nm0, sa[2*kc  ][1] - nm0);
            unsigned a1 = pack_h2(sa[2*kc  ][2] - nm1, sa[2*kc  ][3] - nm1);
            unsigned a2 = pack_h2(sa[2*kc+1][0] - nm0, sa[2*kc+1][1] - nm0);
            unsigned a3 = pack_h2(sa[2*kc+1][2] - nm1, sa[2*kc+1][3] - nm1);
            H2EX2(a0, a0); H2EX2(a1, a1); H2EX2(a2, a2); H2EX2(a3, a3);

            const unsigned raddr = vSm + s*FTILE +
                (((kc*16 + lmRow) * FKST) + lmSel*8) * 2;
#pragma unroll
            for (int np = 0; np < 4; ++np) {
                unsigned b0, b1, b2, b3;
                LDSM_X4_TRANS(b0, b1, b2, b3, raddr + np*32);
                MMA_F16(oa[2*np  ][0], oa[2*np  ][1], oa[2*np  ][2], oa[2*np  ][3],
                        a0, a1, a2, a3, b0, b1);
                MMA_F16(oa[2*np+1][0], oa[2*np+1][1], oa[2*np+1][2], oa[2*np+1][3],
                        a0, a1, a2, a3, b2, b3);
            }
            unsigned s0, s1;
            LDSM_X2_TRANS(s0, s1, vSm + s*FTILE + ((kc*16 + lmRow)*FKST + 64)*2);
            MMA_F16(oaS[0], oaS[1], oaS[2], oaS[3], a0, a1, a2, a3, s0, s1);
        }
    }
#undef F_ISSUE

    const float l0 = __shfl_sync(0xffffffffu, oaS[0], lane & ~3);
    const float l1 = __shfl_sync(0xffffffffu, oaS[2], lane & ~3);
    const int b = bh / NH, hh = bh % NH;
    const float inv0 = 1.f / l0;
    const float inv1 = 1.f / l1;
    __half* d0 = g_A16 + ((size_t)(b*TT + qi0))*DD + hh*DH;
    __half* d1 = g_A16 + ((size_t)(b*TT + qi1))*DD + hh*DH;
#pragma unroll
    for (int nt = 0; nt < 8; ++nt) {
        const int c = nt*8 + 2*qk;
        *(unsigned*)&d0[c] = pack_h2(oa[nt][0]*inv0, oa[nt][1]*inv0);
        *(unsigned*)&d1[c] = pack_h2(oa[nt][2]*inv1, oa[nt][3]*inv1);
    }
}

// ---------------------------------------------------------------------------
extern "C" void kernel_launch(void* const* d_in, const int* in_sizes, int n_in,
                              void* d_out, int out_size)
{
    const float* h  = (const float*)d_in[0];
    const float* wq = (const float*)d_in[1];
    const float* wk = (const float*)d_in[2];
    const float* wv = (const float*)d_in[3];
    const float* wo = (const float*)d_in[4];
    float* out = (float*)d_out;
    (void)in_sizes; (void)n_in; (void)out_size;

    cudaFuncSetAttribute(hgemm16_qkv, cudaFuncAttributeMaxDynamicSharedMemorySize, GSMEM);
    cudaFuncSetAttribute(hgemm16_out, cudaFuncAttributeMaxDynamicSharedMemorySize, GSMEM);

    cvt5<<<dim3(BT*DD/(256*8), 5), 256>>>(h, wq, wk, wv, wo);
    rope_fill<<<TT*32/256, 256>>>();

    hgemm16_qkv<<<dim3(DD/128, BT/128, 3), 256, GSMEM>>>();

    flash16<<<dim3(TT/128, BB*NH), 256>>>();

    hgemm16_out<<<dim3(DD/128, BT/128), 256, GSMEM>>>(out);
}

// round 15
// speedup vs baseline: 1.0188x; 1.0188x over previous
#include <cuda_runtime.h>
#include <cuda_fp16.h>
#include <math.h>

#define BB 2
#define TT 2048
#define DD 1024
#define NH 16
#define DH 64
#define BT (BB*TT)

// fp16 scratch (allocation-free rule: __device__ globals)
__device__ __align__(16) __half g_h16[BT*DD];
__device__ __align__(16) __half g_w16[4][DD*DD];
__device__ __align__(16) __half g_Qh[BB*NH*TT*DH];
__device__ __align__(16) __half g_Kh[BB*NH*TT*DH];
__device__ __align__(16) __half g_Vh[BB*NH*TT*DH];
__device__ __align__(16) __half g_A16[BT*DD];

__device__ __forceinline__ unsigned pack_h2(float x, float y) {
    unsigned r;
    asm("cvt.rn.f16x2.f32 %0, %1, %2;" : "=r"(r) : "f"(y), "f"(x));
    return r;
}
__device__ __forceinline__ unsigned smem_u32(const void* p) {
    return (unsigned)__cvta_generic_to_shared(p);
}
__device__ __forceinline__ float fex2(float x) {
    float r;
    asm("ex2.approx.f32 %0, %1;" : "=f"(r) : "f"(x));
    return r;
}
#define H2EX2(d, s) asm("ex2.approx.f16x2 %0, %1;" : "=r"(d) : "r"(s))
#define H2MUL(d, a, b) asm("mul.rn.f16x2 %0, %1, %2;" : "=r"(d) : "r"(a), "r"(b))

#define MMA_F16(d0,d1,d2,d3,a0,a1,a2,a3,b0,b1)                                    \
    asm volatile("mma.sync.aligned.m16n8k16.row.col.f32.f16.f16.f32 "             \
                 "{%0,%1,%2,%3},{%4,%5,%6,%7},{%8,%9},{%0,%1,%2,%3};"             \
                 : "+f"(d0), "+f"(d1), "+f"(d2), "+f"(d3)                         \
                 : "r"(a0), "r"(a1), "r"(a2), "r"(a3), "r"(b0), "r"(b1))

#define LDSM_X4(r0,r1,r2,r3,addr)                                                 \
    asm volatile("ldmatrix.sync.aligned.m8n8.x4.shared.b16 "                      \
                 "{%0,%1,%2,%3}, [%4];"                                           \
                 : "=r"(r0), "=r"(r1), "=r"(r2), "=r"(r3) : "r"(addr))

#define LDSM_X4_TRANS(r0,r1,r2,r3,addr)                                           \
    asm volatile("ldmatrix.sync.aligned.m8n8.x4.trans.shared.b16 "                \
                 "{%0,%1,%2,%3}, [%4];"                                           \
                 : "=r"(r0), "=r"(r1), "=r"(r2), "=r"(r3) : "r"(addr))

#define LDSM_X2_TRANS(r0,r1,addr)                                                 \
    asm volatile("ldmatrix.sync.aligned.m8n8.x2.trans.shared.b16 "                \
                 "{%0,%1}, [%2];"                                                 \
                 : "=r"(r0), "=r"(r1) : "r"(addr))

#define CP_ASYNC16(dst, src)                                                      \
    asm volatile("cp.async.cg.shared.global [%0], [%1], 16;" :: "r"(dst), "l"(src))
#define CP_COMMIT() asm volatile("cp.async.commit_group;")
#define CP_WAIT0()  asm volatile("cp.async.wait_group 0;")
#define CP_WAIT1()  asm volatile("cp.async.wait_group 1;")

// ---------------------------------------------------------------------------
// fp32 -> fp16 conversion: segment 0 = h (4M), 1-4 = weights (1M each)
// ---------------------------------------------------------------------------
__global__ void cvt5(const float* __restrict__ h,  const float* __restrict__ wq,
                     const float* __restrict__ wk, const float* __restrict__ wv,
                     const float* __restrict__ wo)
{
    const float* src; __half* dst; int n;
    switch (blockIdx.y) {
        case 0: src = h;  dst = g_h16;     n = BT*DD; break;
        case 1: src = wq; dst = g_w16[0];  n = DD*DD; break;
        case 2: src = wk; dst = g_w16[1];  n = DD*DD; break;
        case 3: src = wv; dst = g_w16[2];  n = DD*DD; break;
        default:src = wo; dst = g_w16[3];  n = DD*DD; break;
    }
    const int idx = (blockIdx.x * blockDim.x + threadIdx.x) * 8;
    if (idx >= n) return;
    float4 v0 = *(const float4*)(src + idx);
    float4 v1 = *(const float4*)(src + idx + 4);
    uint4 u = make_uint4(pack_h2(v0.x, v0.y), pack_h2(v0.z, v0.w),
                         pack_h2(v1.x, v1.y), pack_h2(v1.z, v1.w));
    *(uint4*)&dst[idx] = u;
}

// ---------------------------------------------------------------------------
// fp16 cp.async GEMM NT (R12 winner config): CTA tile 128x64, BK=64,
// 3-stage pipeline, 256 thr = 8 warps (4 M x 2 N), warp tile 32x32
// (acc = 32 regs) -> 3 CTAs/SM. Canonical SW128 swizzle, ldmatrix.x4.
// MODE 0: fp32 C row-major.  MODE 1: fp16 C head layout + inline RoPE.
// ---------------------------------------------------------------------------
#define BKG    64
#define NKTG   (DD/BKG)       // 16
#define OPA    16384          // A tile: 128 rows x 128B
#define OPBB   8192           // B tile:  64 rows x 128B
#define STGG   (OPA + OPBB)   // 24576 per stage
#define GSMEM  (3*STGG)       // 73728

__device__ __forceinline__ unsigned swz128(int row, int chunk) {
    return (unsigned)(row << 7) + (unsigned)(((chunk ^ (row & 7)) & 7) << 4);
}

template<int MODE>
__device__ __forceinline__
void hgemm16_body(const __half* __restrict__ A, const __half* __restrict__ W,
                  float* __restrict__ Cf, __half* __restrict__ Ch,
                  int rowBase, int colBase, int doRope)
{
    extern __shared__ __half dsm[];
    const unsigned aSm = smem_u32(dsm);

    const int tid  = threadIdx.x;
    const int lane = tid & 31;
    const int warp = tid >> 5;
    const int grp  = lane >> 2;
    const int qk   = lane & 3;
    const int warpM = (warp & 3) * 32;      // 4 M-slots
    const int warpN = (warp >> 2) * 32;     // 2 N-slots
    const int lmRow = lane & 15;
    const int lmSel = lane >> 4;

    float acc[2][4][4];
#pragma unroll
    for (int mt = 0; mt < 2; ++mt)
#pragma unroll
        for (int nt = 0; nt < 4; ++nt)
#pragma unroll
            for (int r = 0; r < 4; ++r) acc[mt][nt][r] = 0.f;

    const __half* Ab = A + (size_t)rowBase * DD;
    const __half* Wb = W + (size_t)colBase * DD;

#define G_ISSUE(t, s)                                                         \
    do {                                                                      \
        const unsigned sb = aSm + (s) * STGG;                                 \
        _Pragma("unroll")                                                     \
        for (int i = 0; i < 4; ++i) {                                         \
            const int id = tid + 256*i;                                       \
            const int r = id >> 3, c = id & 7;                                \
            CP_ASYNC16(sb + swz128(r, c),                                     \
                       Ab + (size_t)r * DD + (t)*BKG + c*8);                  \
        }                                                                     \
        _Pragma("unroll")                                                     \
        for (int i = 0; i < 2; ++i) {                                         \
            const int id = tid + 256*i;                                       \
            const int r = id >> 3, c = id & 7;                                \
            CP_ASYNC16(sb + OPA + swz128(r, c),                               \
                       Wb + (size_t)r * DD + (t)*BKG + c*8);                  \
        }                                                                     \
        CP_COMMIT();                                                          \
    } while (0)

    G_ISSUE(0, 0);
    G_ISSUE(1, 1);

    int buf = 0;
    for (int t = 0; t < NKTG; ++t) {
        if (t + 1 < NKTG) { CP_WAIT1(); } else { CP_WAIT0(); }
        __syncthreads();
        if (t + 2 < NKTG) G_ISSUE(t + 2, (t + 2) % 3);

        const unsigned ab = aSm + buf * STGG;
        const unsigned bb = ab + OPA;
#pragma unroll
        for (int kc = 0; kc < 4; ++kc) {
            const int ch = kc * 2 + lmSel;
            unsigned a[2][4];
#pragma unroll
            for (int mt = 0; mt < 2; ++mt)
                LDSM_X4(a[mt][0], a[mt][1], a[mt][2], a[mt][3],
                        ab + swz128(warpM + mt*16 + lmRow, ch));
            unsigned bl[4], bh[4];
#pragma unroll
            for (int nc = 0; nc < 2; ++nc) {
                unsigned x0, x1, x2, x3;
                LDSM_X4(x0, x1, x2, x3, bb + swz128(warpN + nc*16 + lmRow, ch));
                bl[2*nc] = x0; bl[2*nc+1] = x1;
                bh[2*nc] = x2; bh[2*nc+1] = x3;
            }
#pragma unroll
            for (int mt = 0; mt < 2; ++mt)
#pragma unroll
                for (int nt = 0; nt < 4; ++nt)
                    MMA_F16(acc[mt][nt][0], acc[mt][nt][1],
                            acc[mt][nt][2], acc[mt][nt][3],
                            a[mt][0], a[mt][1], a[mt][2], a[mt][3],
                            bl[nt], bh[nt]);
        }
        buf = (buf + 1) % 3;
    }
#undef G_ISSUE

#pragma unroll
    for (int mt = 0; mt < 2; ++mt) {
#pragma unroll
        for (int nt = 0; nt < 4; ++nt) {
            const int rr = rowBase + warpM + mt*16 + grp;
            const int c  = colBase + warpN + nt*8 + 2*qk;
            float2 v0 = make_float2(acc[mt][nt][0], acc[mt][nt][1]);
            float2 v1 = make_float2(acc[mt][nt][2], acc[mt][nt][3]);
            if (MODE == 0) {
                *(float2*)&Cf[(size_t)rr * DD + c]       = v0;
                *(float2*)&Cf[(size_t)(rr+8) * DD + c]   = v1;
            } else {
                const int hh = c / DH, d = c % DH;
                const int b0 = rr / TT, t0 = rr % TT;
                const int b1 = (rr+8) / TT, t1 = (rr+8) % TT;
                if (doRope) {
                    const int pair = d >> 1;
                    const float freq = powf(10000.0f, -(float)pair * (1.0f/32.0f));
                    float s0, cc0, s1, cc1;
                    sincosf((float)t0 * freq, &s0, &cc0);
                    sincosf((float)t1 * freq, &s1, &cc1);
                    v0 = make_float2(cc0*v0.x - s0*v0.y, s0*v0.x + cc0*v0.y);
                    v1 = make_float2(cc1*v1.x - s1*v1.y, s1*v1.x + cc1*v1.y);
                }
                *(unsigned*)&Ch[(((size_t)(b0*NH + hh))*TT + t0)*DH + d] =
                    pack_h2(v0.x, v0.y);
                *(unsigned*)&Ch[(((size_t)(b1*NH + hh))*TT + t1)*DH + d] =
                    pack_h2(v1.x, v1.y);
            }
        }
    }
}

__global__ __launch_bounds__(256, 3)
void hgemm16_qkv()
{
    const int z = blockIdx.z;
    __half* C = (z == 0) ? g_Qh : (z == 1) ? g_Kh : g_Vh;
    hgemm16_body<1>(g_h16, g_w16[z], nullptr, C,
                    blockIdx.y * 128, blockIdx.x * 64, z < 2);
}

__global__ __launch_bounds__(256, 3)
void hgemm16_out(float* __restrict__ out)
{
    hgemm16_body<0>(g_A16, g_w16[3], out, nullptr,
                    blockIdx.y * 128, blockIdx.x * 64, 0);
}

// ---------------------------------------------------------------------------
// fp16 flash attention: log2-domain ex2 softmax, ones-column row-sum MMA,
// cp.async double-buffered K/V.
// NEW: Q fragments pre-scaled by (1/sqrt(dh))*log2(e) (kills per-tile S
// scaling); O/l rescale skipped via warp ballot when row max unchanged.
// ---------------------------------------------------------------------------
#define FKST  72
#define FTILE (64*FKST*2)

__global__ __launch_bounds__(256, 2)
void flash16()
{
    __shared__ __half sK[2*64*FKST];
    __shared__ __half sV[2*64*FKST];
    const unsigned kSm = smem_u32(sK);
    const unsigned vSm = smem_u32(sV);

    const int tid  = threadIdx.x;
    const int lane = tid & 31;
    const int warp = tid >> 5;
    const int grp  = lane >> 2;
    const int qk   = lane & 3;
    const int qtile = gridDim.x - 1 - blockIdx.x;
    const int bh    = blockIdx.y;
    const int qbase = qtile * 128;

    const __half* Qp = g_Qh + (size_t)bh * TT * DH;
    const __half* Kp = g_Kh + (size_t)bh * TT * DH;
    const __half* Vp = g_Vh + (size_t)bh * TT * DH;

    const int lmRow = lane & 15;
    const int lmSel = lane >> 4;

    const int qi0 = qbase + warp*16 + grp;
    const int qi1 = qi0 + 8;
    unsigned qa[4][4];
    {
        const __half* q0 = Qp + (size_t)qi0 * DH;
        const __half* q1 = Qp + (size_t)qi1 * DH;
        const float sc2 = 0.125f * 1.44269504f;   // (1/sqrt(dh))*log2(e)
        const unsigned sch = pack_h2(sc2, sc2);
#pragma unroll
        for (int kc = 0; kc < 4; ++kc) {
            qa[kc][0] = *(const unsigned*)(q0 + kc*16 + 2*qk);
            qa[kc][1] = *(const unsigned*)(q1 + kc*16 + 2*qk);
            qa[kc][2] = *(const unsigned*)(q0 + kc*16 + 8 + 2*qk);
            qa[kc][3] = *(const unsigned*)(q1 + kc*16 + 8 + 2*qk);
            H2MUL(qa[kc][0], qa[kc][0], sch);
            H2MUL(qa[kc][1], qa[kc][1], sch);
            H2MUL(qa[kc][2], qa[kc][2], sch);
            H2MUL(qa[kc][3], qa[kc][3], sch);
        }
    }

    float m0 = -1e30f, m1 = -1e30f;
    float oa[8][4];
    float oaS[4] = {0.f, 0.f, 0.f, 0.f};
#pragma unroll
    for (int nt = 0; nt < 8; ++nt)
#pragma unroll
        for (int r = 0; r < 4; ++r) oa[nt][r] = 0.f;

    if (tid < 128) {
        const int rr = tid & 63, ss = tid >> 6;
        *(uint4*)&sV[ss*64*FKST + rr*FKST + 64] = make_uint4(0x00003C00u, 0u, 0u, 0u);
    }

    const int fr = tid >> 3;
    const int fc = tid & 7;
    const unsigned dk0 = (fr*FKST + fc*8) * 2;
    const unsigned dk1 = ((fr+32)*FKST + fc*8) * 2;

#define F_ISSUE(kt, s)                                                        \
    do {                                                                      \
        const __half* ks_ = Kp + (size_t)((kt)*64 + fr) * DH + fc*8;          \
        const __half* vs_ = Vp + (size_t)((kt)*64 + fr) * DH + fc*8;          \
        CP_ASYNC16(kSm + (s)*FTILE + dk0, ks_);                               \
        CP_ASYNC16(kSm + (s)*FTILE + dk1, ks_ + (size_t)32*DH);               \
        CP_ASYNC16(vSm + (s)*FTILE + dk0, vs_);                               \
        CP_ASYNC16(vSm + (s)*FTILE + dk1, vs_ + (size_t)32*DH);               \
        CP_COMMIT();                                                          \
    } while (0)

    F_ISSUE(0, 0);

    const int lastKt = 2*qtile + 1;
    for (int kt = 0; kt <= lastKt; ++kt) {
        const int kbase = kt * 64;
        const int s = kt & 1;
        CP_WAIT0();
        __syncthreads();
        if (kt < lastKt) F_ISSUE(kt + 1, (kt + 1) & 1);

        // ---- S = (scaled Q) K^T : already in log2 domain ----
        float sa[8][4];
#pragma unroll
        for (int nt = 0; nt < 8; ++nt)
#pragma unroll
            for (int r = 0; r < 4; ++r) sa[nt][r] = 0.f;

#pragma unroll
        for (int kc = 0; kc < 4; ++kc) {
#pragma unroll
            for (int nc = 0; nc < 4; ++nc) {
                unsigned x0, x1, x2, x3;
                const unsigned addr = kSm + s*FTILE +
                    ((nc*16 + lmRow)*FKST + (kc*2 + lmSel)*8) * 2;
                LDSM_X4(x0, x1, x2, x3, addr);
                MMA_F16(sa[2*nc  ][0], sa[2*nc  ][1], sa[2*nc  ][2], sa[2*nc  ][3],
                        qa[kc][0], qa[kc][1], qa[kc][2], qa[kc][3], x0, x2);
                MMA_F16(sa[2*nc+1][0], sa[2*nc+1][1], sa[2*nc+1][2], sa[2*nc+1][3],
                        qa[kc][0], qa[kc][1], qa[kc][2], qa[kc][3], x1, x3);
            }
        }

        // ---- causal mask (select only; no scaling needed) ----
        if (kbase + 63 > qbase) {
#pragma unroll
            for (int nt = 0; nt < 8; ++nt) {
                const int c0 = kbase + nt*8 + 2*qk;
                const int c1 = c0 + 1;
                sa[nt][0] = (c0 <= qi0) ? sa[nt][0] : -1e30f;
                sa[nt][1] = (c1 <= qi0) ? sa[nt][1] : -1e30f;
                sa[nt][2] = (c0 <= qi1) ? sa[nt][2] : -1e30f;
                sa[nt][3] = (c1 <= qi1) ? sa[nt][3] : -1e30f;
            }
        }

        // ---- row max ----
        float mx0 = sa[0][0], mx1 = sa[0][2];
#pragma unroll
        for (int nt = 0; nt < 8; ++nt) {
            mx0 = fmaxf(mx0, fmaxf(sa[nt][0], sa[nt][1]));
            mx1 = fmaxf(mx1, fmaxf(sa[nt][2], sa[nt][3]));
        }
        mx0 = fmaxf(mx0, __shfl_xor_sync(0xffffffffu, mx0, 1));
        mx0 = fmaxf(mx0, __shfl_xor_sync(0xffffffffu, mx0, 2));
        mx1 = fmaxf(mx1, __shfl_xor_sync(0xffffffffu, mx1, 1));
        mx1 = fmaxf(mx1, __shfl_xor_sync(0xffffffffu, mx1, 2));

        const float nm0 = fmaxf(m0, mx0);
        const float nm1 = fmaxf(m1, mx1);

        // ---- rescale O/l only when some row max moved (warp-uniform) ----
        if (__ballot_sync(0xffffffffu, (nm0 > m0) || (nm1 > m1))) {
            const float al0 = fex2(m0 - nm0);
            const float al1 = fex2(m1 - nm1);
#pragma unroll
            for (int nt = 0; nt < 8; ++nt) {
                oa[nt][0] *= al0; oa[nt][1] *= al0;
                oa[nt][2] *= al1; oa[nt][3] *= al1;
            }
            oaS[0] *= al0; oaS[1] *= al0;
            oaS[2] *= al1; oaS[3] *= al1;
        }
        m0 = nm0; m1 = nm1;

        // ---- O += P V, l += P·1 : P = ex2.f16x2(s - m) in-register ----
#pragma unroll
        for (int kc = 0; kc < 4; ++kc) {
            unsigned a0 = pack_h2(sa[2*kc  ][0] - nm0, sa[2*kc  ][1] - nm0);
            unsigned a1 = pack_h2(sa[2*kc  ][2] - nm1, sa[2*kc  ][3] - nm1);
            unsigned a2 = pack_h2(sa[2*kc+1][0] - nm0, sa[2*kc+1][1] - nm0);
            unsigned a3 = pack_h2(sa[2*kc+1][2] - nm1, sa[2*kc+1][3] - nm1);
            H2EX2(a0, a0); H2EX2(a1, a1); H2EX2(a2, a2); H2EX2(a3, a3);

            const unsigned raddr = vSm + s*FTILE +
                (((kc*16 + lmRow) * FKST) + lmSel*8) * 2;
#pragma unroll
            for (int np = 0; np < 4; ++np) {
                unsigned b0, b1, b2, b3;
                LDSM_X4_TRANS(b0, b1, b2, b3, raddr + np*32);
                MMA_F16(oa[2*np  ][0], oa[2*np  ][1], oa[2*np  ][2], oa[2*np  ][3],
                        a0, a1, a2, a3, b0, b1);
                MMA_F16(oa[2*np+1][0], oa[2*np+1][1], oa[2*np+1][2], oa[2*np+1][3],
                        a0, a1, a2, a3, b2, b3);
            }
            unsigned s0, s1;
            LDSM_X2_TRANS(s0, s1, vSm + s*FTILE + ((kc*16 + lmRow)*FKST + 64)*2);
            MMA_F16(oaS[0], oaS[1], oaS[2], oaS[3], a0, a1, a2, a3, s0, s1);
        }
    }
#undef F_ISSUE

    const float l0 = __shfl_sync(0xffffffffu, oaS[0], lane & ~3);
    const float l1 = __shfl_sync(0xffffffffu, oaS[2], lane & ~3);
    const int b = bh / NH, hh = bh % NH;
    const float inv0 = 1.f / l0;
    const float inv1 = 1.f / l1;
    __half* d0 = g_A16 + ((size_t)(b*TT + qi0))*DD + hh*DH;
    __half* d1 = g_A16 + ((size_t)(b*TT + qi1))*DD + hh*DH;
#pragma unroll
    for (int nt = 0; nt < 8; ++nt) {
        const int c = nt*8 + 2*qk;
        *(unsigned*)&d0[c] = pack_h2(oa[nt][0]*inv0, oa[nt][1]*inv0);
        *(unsigned*)&d1[c] = pack_h2(oa[nt][2]*inv1, oa[nt][3]*inv1);
    }
}

// ---------------------------------------------------------------------------
extern "C" void kernel_launch(void* const* d_in, const int* in_sizes, int n_in,
                              void* d_out, int out_size)
{
    const float* h  = (const float*)d_in[0];
    const float* wq = (const float*)d_in[1];
    const float* wk = (const float*)d_in[2];
    const float* wv = (const float*)d_in[3];
    const float* wo = (const float*)d_in[4];
    float* out = (float*)d_out;
    (void)in_sizes; (void)n_in; (void)out_size;

    cudaFuncSetAttribute(hgemm16_qkv, cudaFuncAttributeMaxDynamicSharedMemorySize, GSMEM);
    cudaFuncSetAttribute(hgemm16_out, cudaFuncAttributeMaxDynamicSharedMemorySize, GSMEM);

    cvt5<<<dim3(BT*DD/(256*8), 5), 256>>>(h, wq, wk, wv, wo);

    hgemm16_qkv<<<dim3(DD/64, BT/128, 3), 256, GSMEM>>>();

    flash16<<<dim3(TT/128, BB*NH), 256>>>();

    hgemm16_out<<<dim3(DD/64, BT/128), 256, GSMEM>>>(out);
}